// round 1
// baseline (speedup 1.0000x reference)
#include <cuda_runtime.h>
#include <cstdint>
#include <math.h>

#define T_TOK 2048
#define NE 8
#define DDIM 768
#define HDIM 3072
#define NSLOT (T_TOK * 2)

#define BM 128
#define BN 128
#define BK 16

// ---------------- scratch (device globals; no allocations allowed) ----------
__device__ float g_h[(size_t)NSLOT * HDIM];   // h, then act in place   (~50 MB)
__device__ float g_g[(size_t)NSLOT * HDIM];   // g                      (~50 MB)
__device__ float g_y[(size_t)NSLOT * DDIM];   // per-slot expert output (~12.6 MB)
__device__ int   g_cnt[NE];
__device__ int   g_cnt2[NE];
__device__ int   g_off[NE];
__device__ float g_probs[NE];
__device__ int   g_slot_token[NSLOT];
__device__ int   g_tok_slot[NSLOT];
__device__ float g_tok_gate[NSLOT];
__device__ int   g_tok_exp[NSLOT];

// ---------------- kernels ---------------------------------------------------
__global__ void zero_stats()
{
    int i = threadIdx.x;
    if (i < NE) { g_cnt[i] = 0; g_probs[i] = 0.f; }
}

__global__ void gate_kernel(const float* __restrict__ x,
                            const float* __restrict__ noise,
                            const float* __restrict__ gw,
                            const float* __restrict__ nw,
                            float* __restrict__ out_ids)
{
    int t = blockIdx.x;
    int tid = threadIdx.x;              // 128 threads
    const float* xr = x + (size_t)t * DDIM;

    float acc[NE];
#pragma unroll
    for (int e = 0; e < NE; e++) acc[e] = 0.f;

    for (int d = tid; d < DDIM; d += 128) {
        float xv = xr[d];
        const float* w = gw + d * NE;
#pragma unroll
        for (int e = 0; e < NE; e++) acc[e] += xv * w[e];
    }

    __shared__ float sm[NE][128];
#pragma unroll
    for (int e = 0; e < NE; e++) sm[e][tid] = acc[e];
    __syncthreads();
    for (int s = 64; s > 0; s >>= 1) {
        if (tid < s) {
#pragma unroll
            for (int e = 0; e < NE; e++) sm[e][tid] += sm[e][tid + s];
        }
        __syncthreads();
    }

    if (tid == 0) {
        float lg[NE], ns[NE];
#pragma unroll
        for (int e = 0; e < NE; e++) {
            lg[e] = sm[e][0];
            ns[e] = lg[e] + noise[t * NE + e] * nw[e];
        }
        // top-2 (strict >, so ties keep the lower index, matching jax top_k)
        int i0 = 0;
#pragma unroll
        for (int e = 1; e < NE; e++) if (ns[e] > ns[i0]) i0 = e;
        int i1 = (i0 == 0) ? 1 : 0;
#pragma unroll
        for (int e = 0; e < NE; e++) if (e != i0 && ns[e] > ns[i1]) i1 = e;

        float q  = expf(ns[i1] - ns[i0]);   // <= 1
        float p1 = q / (1.f + q);
        float p0 = 1.f - p1;

        g_tok_exp[t * 2 + 0] = i0;  g_tok_exp[t * 2 + 1] = i1;
        g_tok_gate[t * 2 + 0] = p0; g_tok_gate[t * 2 + 1] = p1;
        if (out_ids) {
            out_ids[t * 2 + 0] = (float)i0;
            out_ids[t * 2 + 1] = (float)i1;
        }
        atomicAdd(&g_cnt[i0], 1);
        atomicAdd(&g_cnt[i1], 1);

        // clean-logit softmax for the load-balance loss
        float m = lg[0];
#pragma unroll
        for (int e = 1; e < NE; e++) m = fmaxf(m, lg[e]);
        float ex[NE], sum = 0.f;
#pragma unroll
        for (int e = 0; e < NE; e++) { ex[e] = expf(lg[e] - m); sum += ex[e]; }
        float inv = 1.f / sum;
#pragma unroll
        for (int e = 0; e < NE; e++) atomicAdd(&g_probs[e], ex[e] * inv);
    }
}

__global__ void finalize_kernel(float* __restrict__ out_lb)
{
    if (threadIdx.x == 0 && blockIdx.x == 0) {
        int off = 0;
        for (int e = 0; e < NE; e++) {
            g_off[e] = off;
            off += g_cnt[e];
            g_cnt2[e] = 0;
        }
        float accv = 0.f;
        for (int e = 0; e < NE; e++) {
            float d = g_probs[e] / (float)T_TOK - 1.0f / (float)NE;
            accv += d * d;
        }
        if (out_lb) out_lb[0] = accv / (float)NE * 0.01f;
    }
}

__global__ void scatter_kernel()
{
    int t = blockIdx.x * blockDim.x + threadIdx.x;
    if (t >= T_TOK) return;
#pragma unroll
    for (int k2 = 0; k2 < 2; k2++) {
        int e = g_tok_exp[t * 2 + k2];
        int pos = atomicAdd(&g_cnt2[e], 1);
        int slot = g_off[e] + pos;
        g_slot_token[slot] = t;
        g_tok_slot[t * 2 + k2] = slot;
    }
}

// Grouped SGEMM: C[off[e]+m, n] = sum_k A[m,k] * W[e,k,n] + bias[e,n]
// mode 0: A = x gathered rows -> C = g_h
// mode 1: A = x gathered rows -> C = g_g
// mode 2: A = g_h (dense per-expert slot rows) -> C = g_y
__global__ __launch_bounds__(256, 2)
void sgemm_kernel(const float* __restrict__ X,
                  const float* __restrict__ W,
                  const float* __restrict__ bias,
                  int Kdim, int Ndim, int mode)
{
    int e = blockIdx.z;
    int cnt = g_cnt[e];
    int mbase = blockIdx.y * BM;
    if (mbase >= cnt) return;
    int off = g_off[e];
    int mrem = cnt - mbase;                 // 1..128 valid rows in this tile
    int n0 = blockIdx.x * BN;

    float* C = (mode == 0) ? g_h : (mode == 1) ? g_g : g_y;
    const float* A = (mode == 2) ? g_h : X;

    // precompute the 2 gathered row pointers this thread loads from
    const float* arp[2];
#pragma unroll
    for (int i = 0; i < 2; i++) {
        int idx = threadIdx.x + i * 256;
        int ar = idx >> 2;
        int r = (ar < mrem) ? ar : 0;       // clamp invalid rows to a valid one
        int slot = off + mbase + r;
        if (mode == 2) arp[i] = A + (size_t)slot * Kdim;
        else           arp[i] = A + (size_t)g_slot_token[slot] * Kdim;
    }
    const float* Wp = W + (size_t)e * Kdim * Ndim + n0;

    __shared__ float As[BK][BM];
    __shared__ float Bs[BK][BN];

    float accv[8][8];
#pragma unroll
    for (int mi = 0; mi < 8; mi++)
#pragma unroll
        for (int ni = 0; ni < 8; ni++) accv[mi][ni] = 0.f;

    int tx = threadIdx.x & 15;
    int ty = threadIdx.x >> 4;
    int mt = ty * 8;
    int nt = tx * 8;

    for (int k0 = 0; k0 < Kdim; k0 += BK) {
#pragma unroll
        for (int i = 0; i < 2; i++) {
            int idx = threadIdx.x + i * 256;
            int ar = idx >> 2, a4 = idx & 3;
            float4 v = *(const float4*)(arp[i] + k0 + a4 * 4);
            As[a4 * 4 + 0][ar] = v.x;
            As[a4 * 4 + 1][ar] = v.y;
            As[a4 * 4 + 2][ar] = v.z;
            As[a4 * 4 + 3][ar] = v.w;
        }
#pragma unroll
        for (int i = 0; i < 2; i++) {
            int idx = threadIdx.x + i * 256;
            int br = idx >> 5, b4 = idx & 31;
            *(float4*)&Bs[br][b4 * 4] =
                *(const float4*)(Wp + (size_t)(k0 + br) * Ndim + b4 * 4);
        }
        __syncthreads();
#pragma unroll
        for (int k = 0; k < BK; k++) {
            float a[8], b[8];
            *(float4*)&a[0] = *(const float4*)&As[k][mt];
            *(float4*)&a[4] = *(const float4*)&As[k][mt + 4];
            *(float4*)&b[0] = *(const float4*)&Bs[k][nt];
            *(float4*)&b[4] = *(const float4*)&Bs[k][nt + 4];
#pragma unroll
            for (int mi = 0; mi < 8; mi++)
#pragma unroll
                for (int ni = 0; ni < 8; ni++)
                    accv[mi][ni] += a[mi] * b[ni];
        }
        __syncthreads();
    }

    float bl[8];
    *(float4*)&bl[0] = *(const float4*)(bias + (size_t)e * Ndim + n0 + nt);
    *(float4*)&bl[4] = *(const float4*)(bias + (size_t)e * Ndim + n0 + nt + 4);

#pragma unroll
    for (int mi = 0; mi < 8; mi++) {
        int gm = mt + mi;
        if (gm < mrem) {
            size_t row = (size_t)(off + mbase + gm);
            float* cp = C + row * Ndim + n0 + nt;
            float4 v0 = make_float4(accv[mi][0] + bl[0], accv[mi][1] + bl[1],
                                    accv[mi][2] + bl[2], accv[mi][3] + bl[3]);
            float4 v1 = make_float4(accv[mi][4] + bl[4], accv[mi][5] + bl[5],
                                    accv[mi][6] + bl[6], accv[mi][7] + bl[7]);
            *(float4*)cp = v0;
            *(float4*)(cp + 4) = v1;
        }
    }
}

__global__ void act_kernel()
{
    size_t i = (size_t)blockIdx.x * blockDim.x + threadIdx.x;  // over float4
    float4* hp = (float4*)g_h;
    const float4* gp = (const float4*)g_g;
    float4 g4 = gp[i];
    float4 h4 = hp[i];
    h4.x = h4.x * (g4.x / (1.f + expf(-g4.x)));
    h4.y = h4.y * (g4.y / (1.f + expf(-g4.y)));
    h4.z = h4.z * (g4.z / (1.f + expf(-g4.z)));
    h4.w = h4.w * (g4.w / (1.f + expf(-g4.w)));
    hp[i] = h4;
}

__global__ void combine_kernel(float* __restrict__ out)
{
    int f = blockIdx.x * blockDim.x + threadIdx.x;  // over float4 of out
    int t = f / (DDIM / 4);
    int j = f % (DDIM / 4);
    int s0 = g_tok_slot[t * 2 + 0];
    int s1 = g_tok_slot[t * 2 + 1];
    float g0 = g_tok_gate[t * 2 + 0];
    float g1 = g_tok_gate[t * 2 + 1];
    const float4* y = (const float4*)g_y;
    float4 a = y[(size_t)s0 * (DDIM / 4) + j];
    float4 b = y[(size_t)s1 * (DDIM / 4) + j];
    float4 o;
    o.x = g0 * a.x + g1 * b.x;
    o.y = g0 * a.y + g1 * b.y;
    o.z = g0 * a.z + g1 * b.z;
    o.w = g0 * a.w + g1 * b.w;
    ((float4*)out)[f] = o;
}

// ---------------- launch -----------------------------------------------------
extern "C" void kernel_launch(void* const* d_in, const int* in_sizes, int n_in,
                              void* d_out, int out_size)
{
    const float* x     = (const float*)d_in[0];
    const float* noise = (const float*)d_in[1];
    const float* gw    = (const float*)d_in[2];
    const float* nw    = (const float*)d_in[3];
    const float* w1    = (const float*)d_in[4];
    const float* b1    = (const float*)d_in[5];
    const float* w2    = (const float*)d_in[6];
    const float* b2    = (const float*)d_in[7];
    const float* wp    = (const float*)d_in[8];
    const float* bp    = (const float*)d_in[9];

    float* out = (float*)d_out;
    float* out_ids = nullptr;
    float* out_lb  = nullptr;
    if (out_size >= T_TOK * DDIM + NSLOT)     out_ids = out + (size_t)T_TOK * DDIM;
    if (out_size >= T_TOK * DDIM + NSLOT + 1) out_lb  = out + (size_t)T_TOK * DDIM + NSLOT;

    zero_stats<<<1, 32>>>();
    gate_kernel<<<T_TOK, 128>>>(x, noise, gw, nw, out_ids);
    finalize_kernel<<<1, 1>>>(out_lb);
    scatter_kernel<<<(T_TOK + 255) / 256, 256>>>();

    dim3 g1(HDIM / BN, T_TOK / BM, NE);   // 24 x 16 x 8
    sgemm_kernel<<<g1, 256>>>(x, w1, b1, DDIM, HDIM, 0);
    sgemm_kernel<<<g1, 256>>>(x, w2, b2, DDIM, HDIM, 1);

    act_kernel<<<(size_t)NSLOT * HDIM / 4 / 256, 256>>>();

    dim3 g2(DDIM / BN, T_TOK / BM, NE);   // 6 x 16 x 8
    sgemm_kernel<<<g2, 256>>>(nullptr, wp, bp, HDIM, DDIM, 2);

    combine_kernel<<<T_TOK * DDIM / 4 / 256, 256>>>(out);
}